// round 8
// baseline (speedup 1.0000x reference)
#include <cuda_runtime.h>
#include <cuda_bf16.h>
#include <mma.h>
#include <math.h>
#include <stdint.h>

using namespace nvcuda;

#define B_BATCH 64
#define T_SEQ   2048
#define D_IN    1024
#define H1_DIM  512
#define H2_DIM  32
#define M_TOTAL (B_BATCH * T_SEQ)   // 131072

#define BM 128
#define BN 256
#define BK 128
#define NT 256
#define LDA 144     // bytes per A smem row (128 data + 16 pad) -> conflict-free ldsm
#define LDB 144

// ---- gemm1 smem byte offsets ----
#define OFF_A0  0                    // 128*144 = 18432
#define OFF_A1  18432
#define OFF_B0  36864                // 256*144 = 36864
#define OFF_B1  73728                // mainloop ends 110592
#define OFF_HF  0                    // epilogue alias: fp32 [128][260] = 133120
#define OFF_B1S 133120               // fp32[256]
#define SMEM_G1 134144

#define QA 25.4f                             // 127 / 5.0 (A quant scale)
#define SC (5.0f / (127.0f * 4064.0f))       // dequant: SA * SW

// ---- device scratch ----
__device__ int8_t        g_W1q[H1_DIM * D_IN];     // [n][k] K-major, 512 KB
__device__ __nv_bfloat16 g_W2bf[H1_DIM * H2_DIM];  // 32 KB
__device__ __nv_bfloat16 g_h[(size_t)M_TOTAL * H1_DIM]; // 128 MB post-ReLU bf16
__device__ float         g_logits[M_TOTAL];        // 512 KB

__device__ __forceinline__ uint32_t pack_bf16x2(float lo, float hi) {
    __nv_bfloat162 v = __floats2bfloat162_rn(lo, hi);
    return (uint32_t)__bfloat16_as_ushort(v.x) | ((uint32_t)__bfloat16_as_ushort(v.y) << 16);
}
__device__ __forceinline__ uint32_t smem_u32(const void* p) {
    uint32_t a;
    asm("{ .reg .u64 t; cvta.to.shared.u64 t, %1; cvt.u32.u64 %0, t; }" : "=r"(a) : "l"(p));
    return a;
}
__device__ __forceinline__ void ldsm4(uint32_t* r, uint32_t addr) {
    asm volatile("ldmatrix.sync.aligned.m8n8.x4.shared.b16 {%0,%1,%2,%3}, [%4];"
                 : "=r"(r[0]), "=r"(r[1]), "=r"(r[2]), "=r"(r[3]) : "r"(addr));
}
__device__ __forceinline__ void imma16832(int* d, const uint32_t* a, const uint32_t* b) {
    asm volatile(
        "mma.sync.aligned.m16n8k32.row.col.s32.s8.s8.s32 "
        "{%0,%1,%2,%3}, {%4,%5,%6,%7}, {%8,%9}, {%0,%1,%2,%3};"
        : "+r"(d[0]), "+r"(d[1]), "+r"(d[2]), "+r"(d[3])
        : "r"(a[0]), "r"(a[1]), "r"(a[2]), "r"(a[3]), "r"(b[0]), "r"(b[1]));
}
__device__ __forceinline__ int q8(float x) {
    int q = __float2int_rn(x * QA);
    return max(-127, min(127, q));
}

// ============================================================
// Prep: W1 -> int8 [n][k] (per-tensor scale 4064); W2 -> bf16
// ============================================================
__global__ void prep_kernel(const float* __restrict__ W1, const float* __restrict__ W2) {
    int i = blockIdx.x * blockDim.x + threadIdx.x;
    if (i < H1_DIM * D_IN) {
        int n = i >> 10, k = i & 1023;
        int q = __float2int_rn(W1[k * H1_DIM + n] * 4064.0f);
        g_W1q[i] = (int8_t)max(-127, min(127, q));
    }
    if (i < H1_DIM * H2_DIM) g_W2bf[i] = __float2bfloat16(W2[i]);
}

// ============================================================
// GEMM1 int8: per CTA 128 rows x 256 cols, K=1024 in 8 tiles of 128
// ============================================================
__device__ __forceinline__ void ldgA_half(const float* __restrict__ Ap, int tid, int h, float4 v[8]) {
#pragma unroll
    for (int it = 0; it < 8; it++) {
        int f = tid + (it + h * 8) * NT;   // 0..4095
        int r = f >> 5;                    // row 0..127
        int q = f & 31;                    // float4 idx (128 floats/row)
        v[it] = *reinterpret_cast<const float4*>(Ap + (long)r * D_IN + q * 4);
    }
}
__device__ __forceinline__ void stsA_half(char* smem, uint32_t aoff, int tid, int h, const float4 v[8]) {
#pragma unroll
    for (int it = 0; it < 8; it++) {
        int f = tid + (it + h * 8) * NT;
        int r = f >> 5;
        int q = f & 31;
        uint32_t p = (uint32_t)(q8(v[it].x) & 0xFF)
                   | ((uint32_t)(q8(v[it].y) & 0xFF) << 8)
                   | ((uint32_t)(q8(v[it].z) & 0xFF) << 16)
                   | ((uint32_t)(q8(v[it].w) & 0xFF) << 24);
        *reinterpret_cast<uint32_t*>(smem + aoff + r * LDA + q * 4) = p;
    }
}
__device__ __forceinline__ void cpB(uint32_t b_base, const int8_t* __restrict__ Bsrc, int tid) {
#pragma unroll
    for (int it = 0; it < 8; it++) {
        int c = tid + it * NT;             // 0..2047
        int row = c >> 3;                  // n-row 0..255
        int ch  = c & 7;                   // 16B chunk
        uint32_t off = (uint32_t)(row * LDB + ch * 16);
        uint64_t g = __cvta_generic_to_global((const void*)(Bsrc + (long)row * D_IN + ch * 16));
        asm volatile("cp.async.cg.shared.global [%0], [%1], 16;" :: "r"(b_base + off), "l"(g));
    }
}

__global__ __launch_bounds__(NT, 1)
void gemm1_kernel(const float* __restrict__ A, const float* __restrict__ b1) {
    extern __shared__ char smem[];
    const uint32_t sb = smem_u32(smem);
    const int tid  = threadIdx.x;
    const int wid  = tid >> 5;
    const int lane = tid & 31;
    const int bid  = blockIdx.x;
    const long m0 = (long)(bid >> 1) * BM;
    const int  n0 = (bid & 1) * BN;

    float* b1s = (float*)(smem + OFF_B1S);
    b1s[tid] = b1[n0 + tid];

    const int wm = wid >> 2;   // 0..1
    const int wn = wid & 3;    // 0..3

    // ldmatrix per-lane base offsets (bytes)
    const uint32_t a_base = (uint32_t)((wm * 64 + (lane & 15)) * LDA + ((lane >> 4) * 16));
    const uint32_t b_base = (uint32_t)((wn * 64 + (lane & 7) + ((lane & 16) ? 8 : 0)) * LDB
                                       + ((lane & 8) ? 16 : 0));

    int acc[4][8][4];
#pragma unroll
    for (int mf = 0; mf < 4; mf++)
#pragma unroll
        for (int nf = 0; nf < 8; nf++)
#pragma unroll
            for (int j = 0; j < 4; j++) acc[mf][nf][j] = 0;

    const float*  Ap = A + m0 * D_IN;
    const int8_t* Bp = g_W1q + (long)n0 * D_IN;
    float4 v[8];

    // ---- prologue: tile 0 ----
    cpB(sb + OFF_B0, Bp, tid);
    asm volatile("cp.async.commit_group;" ::: "memory");
    ldgA_half(Ap, tid, 0, v);
    stsA_half(smem, OFF_A0, tid, 0, v);
    ldgA_half(Ap, tid, 1, v);
    stsA_half(smem, OFF_A0, tid, 1, v);
    asm volatile("cp.async.wait_group 0;" ::: "memory");
    __syncthreads();

    // ---- mainloop: 8 K-tiles of 128 ----
#pragma unroll 1
    for (int t = 0; t < 8; t++) {
        const uint32_t acur = (t & 1) ? OFF_A1 : OFF_A0;
        const uint32_t bcur = (t & 1) ? OFF_B1 : OFF_B0;
        const uint32_t anxt = (t & 1) ? OFF_A0 : OFF_A1;
        const uint32_t bnxt = (t & 1) ? OFF_B0 : OFF_B1;
        const float* Apn = Ap + (t + 1) * BK;

        if (t < 7) {
            cpB(sb + bnxt, Bp + (t + 1) * BK, tid);
            asm volatile("cp.async.commit_group;" ::: "memory");
            ldgA_half(Apn, tid, 0, v);
        }

#pragma unroll
        for (int ks = 0; ks < 4; ks++) {
            uint32_t a[4][4], bb[8][2];
#pragma unroll
            for (int mf = 0; mf < 4; mf++)
                ldsm4(a[mf], sb + acur + a_base + mf * (16 * LDA) + ks * 32);
#pragma unroll
            for (int pr = 0; pr < 4; pr++) {
                uint32_t tmp[4];
                ldsm4(tmp, sb + bcur + b_base + pr * (16 * LDB) + ks * 32);
                bb[2 * pr][0] = tmp[0]; bb[2 * pr][1] = tmp[1];
                bb[2 * pr + 1][0] = tmp[2]; bb[2 * pr + 1][1] = tmp[3];
            }
#pragma unroll
            for (int mf = 0; mf < 4; mf++)
#pragma unroll
                for (int nf = 0; nf < 8; nf++)
                    imma16832(acc[mf][nf], a[mf], bb[nf]);

            if (t < 7) {
                if (ks == 1) { stsA_half(smem, anxt, tid, 0, v); ldgA_half(Apn, tid, 1, v); }
                if (ks == 3) {
                    stsA_half(smem, anxt, tid, 1, v);
                    asm volatile("cp.async.wait_group 0;" ::: "memory");
                }
            }
        }
        __syncthreads();
    }

    // ---- epilogue stage 1: scaled int32 -> fp32 smem ----
    float* Hf = (float*)(smem + OFF_HF);   // [128][260]
    const int er = lane >> 2;
    const int ec = (lane & 3) * 2;
#pragma unroll
    for (int mf = 0; mf < 4; mf++)
#pragma unroll
        for (int nf = 0; nf < 8; nf++) {
            int r0 = wm * 64 + mf * 16 + er;
            int c0 = wn * 64 + nf * 8 + ec;
            const int* d = acc[mf][nf];
            *reinterpret_cast<float2*>(&Hf[r0 * 260 + c0]) =
                make_float2(SC * (float)d[0], SC * (float)d[1]);
            *reinterpret_cast<float2*>(&Hf[(r0 + 8) * 260 + c0]) =
                make_float2(SC * (float)d[2], SC * (float)d[3]);
        }
    __syncthreads();

    // ---- stage 2: bias + relu + bf16 -> global ----
    __nv_bfloat16* hout = g_h + m0 * H1_DIM + n0;
#pragma unroll
    for (int it = 0; it < 32; it++) {
        int f = tid + it * NT;            // 8192 float4
        int r = f >> 6;
        int q = f & 63;
        float4 x = *reinterpret_cast<const float4*>(Hf + r * 260 + q * 4);
        float x0 = fmaxf(x.x + b1s[q * 4 + 0], 0.0f);
        float x1 = fmaxf(x.y + b1s[q * 4 + 1], 0.0f);
        float x2 = fmaxf(x.z + b1s[q * 4 + 2], 0.0f);
        float x3 = fmaxf(x.w + b1s[q * 4 + 3], 0.0f);
        uint2 u;
        u.x = pack_bf16x2(x0, x1);
        u.y = pack_bf16x2(x2, x3);
        *reinterpret_cast<uint2*>(hout + (long)r * H1_DIM + q * 4) = u;
    }
}

// ============================================================
// mlp2: 64 rows/CTA: out = h @ W2 + b2; logit = out.W3 + b3; sigmoid
// ============================================================
#define H_LD 528
#define M2_HS   0                     // bf16 [64][528] = 67584
#define M2_OUTS 67584                 // fp32 [64][36] = 9216
#define M2_B2S  76800
#define M2_W3S  76928
#define SMEM_M2 77056

__global__ __launch_bounds__(256, 1)
void mlp2_kernel(const float* __restrict__ b2, const float* __restrict__ W3,
                 const float* __restrict__ b3) {
    extern __shared__ char smem[];
    const uint32_t sb = smem_u32(smem);
    const int tid = threadIdx.x;
    const int wid = tid >> 5;
    const long m0 = (long)blockIdx.x * 64;

    float* b2s = (float*)(smem + M2_B2S);
    float* W3s = (float*)(smem + M2_W3S);
    if (tid < 32)        b2s[tid] = b2[tid];
    else if (tid < 64)   W3s[tid - 32] = W3[tid - 32];

    const __nv_bfloat16* hp = g_h + m0 * H1_DIM;
#pragma unroll
    for (int it = 0; it < 16; it++) {
        int c = tid + it * 256;
        int row = c >> 6;
        int ch  = c & 63;
        uint32_t off = (uint32_t)(M2_HS + row * (H_LD * 2) + ch * 16);
        uint64_t g = __cvta_generic_to_global((const void*)(hp + (long)row * H1_DIM + ch * 8));
        asm volatile("cp.async.cg.shared.global [%0], [%1], 16;" :: "r"(sb + off), "l"(g));
    }
    asm volatile("cp.async.commit_group;" ::: "memory");
    asm volatile("cp.async.wait_group 0;" ::: "memory");
    __syncthreads();

    const __nv_bfloat16* Hs = (const __nv_bfloat16*)(smem + M2_HS);
    float* outs = (float*)(smem + M2_OUTS);
    {
        const int rg = wid >> 1;
        const int cg = wid & 1;
        wmma::fragment<wmma::accumulator, 16, 16, 16, float> acc2;
        wmma::fill_fragment(acc2, 0.0f);
#pragma unroll 4
        for (int kk = 0; kk < 32; kk++) {
            wmma::fragment<wmma::matrix_a, 16, 16, 16, __nv_bfloat16, wmma::row_major> a;
            wmma::fragment<wmma::matrix_b, 16, 16, 16, __nv_bfloat16, wmma::row_major> b;
            wmma::load_matrix_sync(a, Hs + (rg * 16) * H_LD + kk * 16, H_LD);
            wmma::load_matrix_sync(b, g_W2bf + (kk * 16) * H2_DIM + cg * 16, H2_DIM);
            wmma::mma_sync(acc2, a, b, acc2);
        }
        wmma::store_matrix_sync(&outs[(rg * 16) * 36 + cg * 16], acc2, 36, wmma::mem_row_major);
    }
    __syncthreads();

    if (tid < 64) {
        float logit = *b3;
#pragma unroll
        for (int n = 0; n < 32; n++)
            logit += (outs[tid * 36 + n] + b2s[n]) * W3s[n];
        g_logits[m0 + tid] = 1.0f / (1.0f + expf(-logit));
    }
}

// ============================================================
// topk: per-batch bitonic sort + masked top-k mean
// ============================================================
__global__ __launch_bounds__(1024, 1) void topk_kernel(const int* __restrict__ seq_len,
                                                       float* __restrict__ out) {
    __shared__ float vals[2048];
    __shared__ float red[32];
    const int b   = blockIdx.x;
    const int tid = threadIdx.x;
    const int s   = seq_len[b];

    for (int i = tid; i < 2048; i += 1024)
        vals[i] = (i < s) ? g_logits[(long)b * T_SEQ + i] : -INFINITY;
    __syncthreads();

    for (int k = 2; k <= 2048; k <<= 1) {
        for (int j = k >> 1; j > 0; j >>= 1) {
            for (int l = tid; l < 2048; l += 1024) {
                int ixj = l ^ j;
                if (ixj > l) {
                    float a = vals[l], c = vals[ixj];
                    bool up = ((l & k) == 0);
                    if (up ? (a < c) : (a > c)) { vals[l] = c; vals[ixj] = a; }
                }
            }
            __syncthreads();
        }
    }

    const int kb = s / 16 + 1;
    float sum = 0.0f;
    for (int i = tid; i < kb; i += 1024) sum += vals[i];
#pragma unroll
    for (int off = 16; off > 0; off >>= 1)
        sum += __shfl_down_sync(0xffffffffu, sum, off);
    if ((tid & 31) == 0) red[tid >> 5] = sum;
    __syncthreads();
    if (tid == 0) {
        float t = 0.0f;
#pragma unroll
        for (int w = 0; w < 32; w++) t += red[w];
        out[b] = t / (float)kb;
    }
}

// ============================================================
extern "C" void kernel_launch(void* const* d_in, const int* in_sizes, int n_in,
                              void* d_out, int out_size) {
    const float* avf = (const float*)d_in[0];
    const int*   seq = (const int*)  d_in[1];
    const float* W1  = (const float*)d_in[2];
    const float* b1  = (const float*)d_in[3];
    const float* W2  = (const float*)d_in[4];
    const float* b2  = (const float*)d_in[5];
    const float* W3  = (const float*)d_in[6];
    const float* b3  = (const float*)d_in[7];
    float* out = (float*)d_out;

    cudaFuncSetAttribute(gemm1_kernel, cudaFuncAttributeMaxDynamicSharedMemorySize, SMEM_G1);
    cudaFuncSetAttribute(mlp2_kernel,  cudaFuncAttributeMaxDynamicSharedMemorySize, SMEM_M2);

    prep_kernel<<<2048, 256>>>(W1, W2);
    gemm1_kernel<<<(M_TOTAL / BM) * 2, NT, SMEM_G1>>>(avf, b1);
    mlp2_kernel<<<M_TOTAL / 64, 256, SMEM_M2>>>(b2, W3, b3);
    topk_kernel<<<B_BATCH, 1024>>>(seq, out);
}